// round 6
// baseline (speedup 1.0000x reference)
#include <cuda_runtime.h>
#include <cuda_bf16.h>

// ---------------------------------------------------------------------------
// mlp_forward_model_44495861187262
//
// reference math (N=1e6 nodes, G=4096 graphs, hidden=64, node_f=5, out=4):
//   h   = relu(x @ W1a + b1a)                 [N,64]
//   x1  = h @ W1b + b1b                       [N,64]
//   agg = segment_sum(x1, batch)              [G,64]
//   cat = concat([x, agg[batch]], axis=1)     [N,69]
//   h2  = relu(cat @ W2a + b2a)               [N,64]
//   out = h2 @ W2b + b2b                      [N,4]
//
// restructured (segment_sum distributes over the linear layer):
//   aggH   = segment_sum(relu(x@W1a+b1a))            (pass 1: 5x64 per node)
//   agg    = aggH @ W1b + cnt*b1b                    (per graph)
//   G      = agg @ W2a[5:69]                         (per graph)
//   out    = relu(x@W2a[0:5] + G[batch] + b2a) @ W2b + b2b   (pass 2)
//
// batch / edge_index are int32 (JAX default x64 disabled downgrades the
// jnp.int64 request). edge_index is dead in the reference.
// ---------------------------------------------------------------------------

#define N_GRAPHS 4096
#define HIDDEN   64
#define NODE_F   5
#define OUT_F    4

// scratch (allocation-free rule: __device__ globals)
__device__ float g_aggH[N_GRAPHS * HIDDEN];
__device__ float g_cnt[N_GRAPHS];
__device__ float g_G[N_GRAPHS * HIDDEN];

// ---------------------------------------------------------------------------
__global__ void k_zero() {
    int i = blockIdx.x * blockDim.x + threadIdx.x;
    if (i < N_GRAPHS * HIDDEN) g_aggH[i] = 0.0f;
    if (i < N_GRAPHS)          g_cnt[i]  = 0.0f;
}

// ---------------------------------------------------------------------------
// Pass 1: warp processes a contiguous run of nodes; lane owns channels
// (lane, lane+32). batch is sorted -> graph id is warp-uniform; accumulate
// in registers, flush with atomics only on segment change
// (~#graph-boundaries flushes total instead of N*64 atomics).
#define NPW 64   // nodes per warp

__global__ void k_pass1(const float* __restrict__ x,
                        const int* __restrict__ batch,
                        const float* __restrict__ W1a,
                        const float* __restrict__ b1a,
                        int N) {
    int warp = (blockIdx.x * blockDim.x + threadIdx.x) >> 5;
    int lane = threadIdx.x & 31;
    long long start = (long long)warp * NPW;
    if (start >= N) return;
    long long end = start + NPW;
    if (end > N) end = N;

    const int c0 = lane, c1 = lane + 32;

    float w0[NODE_F], w1[NODE_F];
#pragma unroll
    for (int k = 0; k < NODE_F; k++) {
        w0[k] = __ldg(W1a + k * HIDDEN + c0);
        w1[k] = __ldg(W1a + k * HIDDEN + c1);
    }
    const float bb0 = __ldg(b1a + c0);
    const float bb1 = __ldg(b1a + c1);

    unsigned cur_g = (unsigned)__ldg(batch + start);
    if (cur_g >= N_GRAPHS) cur_g = 0;           // safety: never trap
    float acc0 = 0.0f, acc1 = 0.0f, cnt = 0.0f;

    for (long long n = start; n < end; n++) {
        unsigned g = (unsigned)__ldg(batch + n);
        if (g >= N_GRAPHS) g = 0;               // safety: never trap
        if (g != cur_g) {   // warp-uniform branch (batch sorted, node shared by warp)
            atomicAdd(&g_aggH[cur_g * HIDDEN + c0], acc0);
            atomicAdd(&g_aggH[cur_g * HIDDEN + c1], acc1);
            if (lane == 0) atomicAdd(&g_cnt[cur_g], cnt);
            acc0 = 0.0f; acc1 = 0.0f; cnt = 0.0f;
            cur_g = g;
        }
        const float* xp = x + n * NODE_F;
        float x0 = __ldg(xp + 0), x1v = __ldg(xp + 1), x2 = __ldg(xp + 2);
        float x3 = __ldg(xp + 3), x4 = __ldg(xp + 4);

        float h0 = bb0, h1 = bb1;
        h0 = fmaf(x0, w0[0], h0);  h1 = fmaf(x0, w1[0], h1);
        h0 = fmaf(x1v, w0[1], h0); h1 = fmaf(x1v, w1[1], h1);
        h0 = fmaf(x2, w0[2], h0);  h1 = fmaf(x2, w1[2], h1);
        h0 = fmaf(x3, w0[3], h0);  h1 = fmaf(x3, w1[3], h1);
        h0 = fmaf(x4, w0[4], h0);  h1 = fmaf(x4, w1[4], h1);

        acc0 += fmaxf(h0, 0.0f);
        acc1 += fmaxf(h1, 0.0f);
        cnt  += 1.0f;
    }
    atomicAdd(&g_aggH[cur_g * HIDDEN + c0], acc0);
    atomicAdd(&g_aggH[cur_g * HIDDEN + c1], acc1);
    if (lane == 0) atomicAdd(&g_cnt[cur_g], cnt);
}

// ---------------------------------------------------------------------------
// Per-graph: t = aggH@W1b + cnt*b1b ; G = t @ W2a[5:69]
__global__ void k_graph(const float* __restrict__ W1b,
                        const float* __restrict__ b1b,
                        const float* __restrict__ W2a) {
    int g = blockIdx.x;
    int c = threadIdx.x;          // 64 threads
    __shared__ float t[HIDDEN];

    float cntg = g_cnt[g];
    float acc  = cntg * __ldg(b1b + c);
    const float* ah = g_aggH + g * HIDDEN;
#pragma unroll 8
    for (int k = 0; k < HIDDEN; k++)
        acc = fmaf(ah[k], __ldg(W1b + k * HIDDEN + c), acc);
    t[c] = acc;
    __syncthreads();

    float gacc = 0.0f;
#pragma unroll 8
    for (int k = 0; k < HIDDEN; k++)
        gacc = fmaf(t[k], __ldg(W2a + (NODE_F + k) * HIDDEN + c), gacc);
    g_G[g * HIDDEN + c] = gacc;
}

// ---------------------------------------------------------------------------
// Pass 2: thread per node. smem weight row per channel c (stride 12 floats,
// 48B -> float4 aligned): [w0..w3][w4,b2a,wb0,wb1][wb2,wb3,pad,pad]
__global__ void k_pass2(const float* __restrict__ x,
                        const int* __restrict__ batch,
                        const float* __restrict__ W2a,
                        const float* __restrict__ b2a,
                        const float* __restrict__ W2b,
                        const float* __restrict__ b2b,
                        float* __restrict__ out,
                        int N) {
    __shared__ float sw[HIDDEN * 12];
    __shared__ float sx[256 * NODE_F];
    int tid = threadIdx.x;

    if (tid < HIDDEN) {
        int c = tid;
#pragma unroll
        for (int k = 0; k < NODE_F; k++) sw[c * 12 + k] = W2a[k * HIDDEN + c];
        sw[c * 12 + 5] = b2a[c];
#pragma unroll
        for (int j = 0; j < OUT_F; j++) sw[c * 12 + 6 + j] = W2b[c * OUT_F + j];
        sw[c * 12 + 10] = 0.0f; sw[c * 12 + 11] = 0.0f;
    }

    long long base = (long long)blockIdx.x * 256;
    // stage x cooperatively (coalesced gmem; stride-5 smem read is
    // conflict-free since gcd(5,32)=1)
    for (int i = tid; i < 256 * NODE_F; i += 256) {
        long long idx = base * NODE_F + i;
        if (idx < (long long)N * NODE_F) sx[i] = x[idx];
    }
    __syncthreads();

    long long n = base + tid;
    if (n >= N) return;

    unsigned g = (unsigned)__ldg(batch + n);
    if (g >= N_GRAPHS) g = 0;                   // safety: never trap
    const float* Gp = g_G + g * HIDDEN;

    float xv0 = sx[tid * NODE_F + 0];
    float xv1 = sx[tid * NODE_F + 1];
    float xv2 = sx[tid * NODE_F + 2];
    float xv3 = sx[tid * NODE_F + 3];
    float xv4 = sx[tid * NODE_F + 4];

    float o0 = __ldg(b2b + 0), o1 = __ldg(b2b + 1);
    float o2 = __ldg(b2b + 2), o3 = __ldg(b2b + 3);

#pragma unroll 8
    for (int c = 0; c < HIDDEN; c++) {
        float4 f0 = *reinterpret_cast<const float4*>(&sw[c * 12 + 0]);
        float4 f1 = *reinterpret_cast<const float4*>(&sw[c * 12 + 4]);
        float2 f2 = *reinterpret_cast<const float2*>(&sw[c * 12 + 8]);

        float a = f1.y + __ldg(Gp + c);
        a = fmaf(xv0, f0.x, a);
        a = fmaf(xv1, f0.y, a);
        a = fmaf(xv2, f0.z, a);
        a = fmaf(xv3, f0.w, a);
        a = fmaf(xv4, f1.x, a);
        a = fmaxf(a, 0.0f);

        o0 = fmaf(a, f1.z, o0);
        o1 = fmaf(a, f1.w, o1);
        o2 = fmaf(a, f2.x, o2);
        o3 = fmaf(a, f2.y, o3);
    }
    float4 ov = make_float4(o0, o1, o2, o3);
    reinterpret_cast<float4*>(out)[n] = ov;
}

// ---------------------------------------------------------------------------
extern "C" void kernel_launch(void* const* d_in, const int* in_sizes, int n_in,
                              void* d_out, int out_size) {
    const float* x     = (const float*)d_in[0];
    const int*   batch = (const int*)d_in[2];     // int32 (JAX x64 disabled)
    // last 8 inputs are the weights (robust to num_graphs scalar presence)
    int wb = n_in - 8;
    const float* W1a = (const float*)d_in[wb + 0];
    const float* b1a = (const float*)d_in[wb + 1];
    const float* W1b = (const float*)d_in[wb + 2];
    const float* b1b = (const float*)d_in[wb + 3];
    const float* W2a = (const float*)d_in[wb + 4];
    const float* b2a = (const float*)d_in[wb + 5];
    const float* W2b = (const float*)d_in[wb + 6];
    const float* b2b = (const float*)d_in[wb + 7];
    float* out = (float*)d_out;

    int N = in_sizes[0] / NODE_F;

    // K0: zero scratch
    {
        int tot = N_GRAPHS * HIDDEN;
        k_zero<<<(tot + 255) / 256, 256>>>();
    }
    // K1: pass 1 (segment-summed hidden h)
    {
        long long warps = ((long long)N + NPW - 1) / NPW;
        long long threads = warps * 32;
        int blocks = (int)((threads + 255) / 256);
        k_pass1<<<blocks, 256>>>(x, batch, W1a, b1a, N);
    }
    // K2: per-graph GEMMs
    k_graph<<<N_GRAPHS, HIDDEN>>>(W1b, b1b, W2a);
    // K3: pass 2 (output)
    {
        int blocks = (N + 255) / 256;
        k_pass2<<<blocks, 256>>>(x, batch, W2a, b2a, W2b, b2b, out, N);
    }
}

// round 7
// speedup vs baseline: 1.4089x; 1.4089x over previous
#include <cuda_runtime.h>
#include <cuda_bf16.h>

// ---------------------------------------------------------------------------
// mlp_forward_model_44495861187262
//
// restructured (segment_sum distributes over the linear layer):
//   aggH   = segment_sum(relu(x@W1a+b1a))            (pass 1: 5x64 per node)
//   agg    = aggH @ W1b + cnt*b1b                    (per graph)
//   G      = agg @ W2a[5:69] + b2a                   (per graph, b2a folded)
//   out    = relu(x@W2a[0:5] + G[batch]) @ W2b + b2b (pass 2)
//
// batch is int32 (JAX x64 disabled). edge_index is dead in the reference.
// f32x2 packed FFMA (sm_100+) used for all per-node math.
// ---------------------------------------------------------------------------

#define N_GRAPHS 4096
#define HIDDEN   64
#define NODE_F   5
#define OUT_F    4

typedef unsigned long long ull;

// scratch (allocation-free rule: __device__ globals)
__device__ float g_aggH[N_GRAPHS * HIDDEN];
__device__ float g_cnt[N_GRAPHS];
__device__ float g_G[N_GRAPHS * HIDDEN];

// ---- f32x2 helpers ---------------------------------------------------------
__device__ __forceinline__ ull pk2(float lo, float hi) {
    ull r; asm("mov.b64 %0, {%1,%2};" : "=l"(r) : "f"(lo), "f"(hi)); return r;
}
__device__ __forceinline__ ull pkdup(float v) {
    ull r; asm("mov.b64 %0, {%1,%1};" : "=l"(r) : "f"(v)); return r;
}
__device__ __forceinline__ void upk2(ull v, float& lo, float& hi) {
    asm("mov.b64 {%0,%1}, %2;" : "=f"(lo), "=f"(hi) : "l"(v));
}
__device__ __forceinline__ void fma2(ull& d, ull a, ull b) {
    asm("fma.rn.f32x2 %0, %1, %2, %0;" : "+l"(d) : "l"(a), "l"(b));
}
__device__ __forceinline__ void relu2(ull& a) {
    float lo, hi; upk2(a, lo, hi);
    lo = fmaxf(lo, 0.0f); hi = fmaxf(hi, 0.0f);
    a = pk2(lo, hi);
}

// ---------------------------------------------------------------------------
__global__ void k_zero() {
    int i = blockIdx.x * blockDim.x + threadIdx.x;
    if (i < N_GRAPHS * HIDDEN) g_aggH[i] = 0.0f;
    if (i < N_GRAPHS)          g_cnt[i]  = 0.0f;
}

// ---------------------------------------------------------------------------
// Pass 1: warp owns 64 contiguous nodes; lane owns channels (2*lane, 2*lane+1).
// batch sorted -> graph id warp-uniform; register accumulate, atomic flush
// only at segment boundaries. 4-node groups: float4 x loads, int4 batch load,
// single fast-path check (sorted => first==last => all equal).
#define NPW 64

__global__ void k_pass1(const float* __restrict__ x,
                        const int* __restrict__ batch,
                        const float* __restrict__ W1a,
                        const float* __restrict__ b1a,
                        int N) {
    int warp = (blockIdx.x * blockDim.x + threadIdx.x) >> 5;
    int lane = threadIdx.x & 31;
    long long start = (long long)warp * NPW;
    if (start >= N) return;

    const int c0 = 2 * lane;

    ull w2[NODE_F];
#pragma unroll
    for (int k = 0; k < NODE_F; k++) {
        float2 w = __ldg((const float2*)(W1a + k * HIDDEN + c0));
        w2[k] = pk2(w.x, w.y);
    }
    {
        float2 b = __ldg((const float2*)(b1a + c0));
        w2[0] = w2[0]; // no-op
        // bias kept separately below
    }
    float2 bv = __ldg((const float2*)(b1a + c0));
    const ull bias2 = pk2(bv.x, bv.y);

    unsigned cur_g;
    {
        unsigned g = (unsigned)__ldg(batch + start);
        cur_g = (g < N_GRAPHS) ? g : 0u;
    }
    float acc0 = 0.0f, acc1 = 0.0f, cnt = 0.0f;

#define P1_FLUSH() do {                                        \
        atomicAdd(&g_aggH[cur_g * HIDDEN + c0],     acc0);     \
        atomicAdd(&g_aggH[cur_g * HIDDEN + c0 + 1], acc1);     \
        if (lane == 0) atomicAdd(&g_cnt[cur_g], cnt);          \
        acc0 = 0.0f; acc1 = 0.0f; cnt = 0.0f;                  \
    } while (0)

#define P1_NODE(i) do {                                        \
        ull h = bias2;                                         \
        _Pragma("unroll")                                      \
        for (int k = 0; k < NODE_F; k++) {                     \
            ull xp = pkdup(xr[(i) * NODE_F + k]);              \
            fma2(h, xp, w2[k]);                                \
        }                                                      \
        float h0, h1; upk2(h, h0, h1);                         \
        acc0 += fmaxf(h0, 0.0f);                               \
        acc1 += fmaxf(h1, 0.0f);                               \
    } while (0)

    if (start + NPW <= N) {
        const float4* xv = (const float4*)(x + start * NODE_F);
        const int4*   bvv = (const int4*)(batch + start);
#pragma unroll 2
        for (int grp = 0; grp < NPW / 4; grp++) {
            int4 bg = __ldg(bvv + grp);
            float4 v0 = __ldg(xv + grp * 5 + 0);
            float4 v1 = __ldg(xv + grp * 5 + 1);
            float4 v2 = __ldg(xv + grp * 5 + 2);
            float4 v3 = __ldg(xv + grp * 5 + 3);
            float4 v4 = __ldg(xv + grp * 5 + 4);
            float xr[20] = { v0.x, v0.y, v0.z, v0.w,
                             v1.x, v1.y, v1.z, v1.w,
                             v2.x, v2.y, v2.z, v2.w,
                             v3.x, v3.y, v3.z, v3.w,
                             v4.x, v4.y, v4.z, v4.w };
            if ((unsigned)bg.w == cur_g) {      // all 4 nodes in cur_g (sorted)
                P1_NODE(0); P1_NODE(1); P1_NODE(2); P1_NODE(3);
                cnt += 4.0f;
            } else {
                int gs[4] = { bg.x, bg.y, bg.z, bg.w };
#pragma unroll
                for (int i = 0; i < 4; i++) {
                    unsigned g = (unsigned)gs[i];
                    if (g >= N_GRAPHS) g = 0;
                    if (g != cur_g) { P1_FLUSH(); cur_g = g; }
                    P1_NODE(i); cnt += 1.0f;
                }
            }
        }
    } else {
        // scalar tail (unused for N = 1e6, kept for generality)
        long long end = N;
        for (long long n = start; n < end; n++) {
            unsigned g = (unsigned)__ldg(batch + n);
            if (g >= N_GRAPHS) g = 0;
            if (g != cur_g) { P1_FLUSH(); cur_g = g; }
            float xr[NODE_F];
#pragma unroll
            for (int k = 0; k < NODE_F; k++) xr[k] = __ldg(x + n * NODE_F + k);
            ull h = bias2;
#pragma unroll
            for (int k = 0; k < NODE_F; k++) { ull xp = pkdup(xr[k]); fma2(h, xp, w2[k]); }
            float h0, h1; upk2(h, h0, h1);
            acc0 += fmaxf(h0, 0.0f);
            acc1 += fmaxf(h1, 0.0f);
            cnt += 1.0f;
        }
    }
    P1_FLUSH();
#undef P1_NODE
#undef P1_FLUSH
}

// ---------------------------------------------------------------------------
// Per-graph: t = aggH@W1b + cnt*b1b ; G = t @ W2a[5:69] + b2a (b2a folded)
__global__ void k_graph(const float* __restrict__ W1b,
                        const float* __restrict__ b1b,
                        const float* __restrict__ W2a,
                        const float* __restrict__ b2a) {
    int g = blockIdx.x;
    int c = threadIdx.x;          // 64 threads
    __shared__ float t[HIDDEN];

    float cntg = g_cnt[g];
    float acc  = cntg * __ldg(b1b + c);
    const float* ah = g_aggH + g * HIDDEN;
#pragma unroll 8
    for (int k = 0; k < HIDDEN; k++)
        acc = fmaf(ah[k], __ldg(W1b + k * HIDDEN + c), acc);
    t[c] = acc;
    __syncthreads();

    float gacc = __ldg(b2a + c);
#pragma unroll 8
    for (int k = 0; k < HIDDEN; k++)
        gacc = fmaf(t[k], __ldg(W2a + (NODE_F + k) * HIDDEN + c), gacc);
    g_G[g * HIDDEN + c] = gacc;
}

// ---------------------------------------------------------------------------
// Pass 2: 2 nodes per thread, 512 nodes per 256-thread block.
// Weight record per channel pair p (channels 2p,2p+1), 20 floats, 16B-aligned:
//   [0:8)  w_k pairs k=0..3   [8:16) wb_j pairs j=0..3   [16:18) w_4 pair  [18:20) pad
// G rows (with b2a folded) for the block's graph span staged in smem.
#define P2_NODES 512
#define P2_SGMAX 16

__device__ __forceinline__ void p2_pair(
    const float* __restrict__ xsA, const float* __restrict__ xsB,
    const float* __restrict__ GA,  const float* __restrict__ GB,
    const float* __restrict__ swp,
    float4& oA, float4& oB)
{
    ull xpA[NODE_F], xpB[NODE_F];
#pragma unroll
    for (int k = 0; k < NODE_F; k++) { xpA[k] = pkdup(xsA[k]); xpB[k] = pkdup(xsB[k]); }

    ull a0 = 0, a1 = 0, a2 = 0, a3 = 0;   // outA accumulators (packed even/odd)
    ull b0 = 0, b1 = 0, b2 = 0, b3 = 0;   // outB accumulators

#pragma unroll 8
    for (int p = 0; p < HIDDEN / 2; p++) {
        const float* rec = swp + p * 20;
        ulonglong2 q0 = *reinterpret_cast<const ulonglong2*>(rec);      // w0,w1
        ulonglong2 q1 = *reinterpret_cast<const ulonglong2*>(rec + 4);  // w2,w3
        ulonglong2 q2 = *reinterpret_cast<const ulonglong2*>(rec + 8);  // wb0,wb1
        ulonglong2 q3 = *reinterpret_cast<const ulonglong2*>(rec + 12); // wb2,wb3
        ull w4 = *reinterpret_cast<const ull*>(rec + 16);

        ull hA = *reinterpret_cast<const ull*>(GA + 2 * p);
        ull hB = *reinterpret_cast<const ull*>(GB + 2 * p);

        fma2(hA, xpA[0], q0.x); fma2(hB, xpB[0], q0.x);
        fma2(hA, xpA[1], q0.y); fma2(hB, xpB[1], q0.y);
        fma2(hA, xpA[2], q1.x); fma2(hB, xpB[2], q1.x);
        fma2(hA, xpA[3], q1.y); fma2(hB, xpB[3], q1.y);
        fma2(hA, xpA[4], w4);   fma2(hB, xpB[4], w4);

        relu2(hA); relu2(hB);

        fma2(a0, hA, q2.x); fma2(b0, hB, q2.x);
        fma2(a1, hA, q2.y); fma2(b1, hB, q2.y);
        fma2(a2, hA, q3.x); fma2(b2, hB, q3.x);
        fma2(a3, hA, q3.y); fma2(b3, hB, q3.y);
    }
    float lo, hi;
    upk2(a0, lo, hi); oA.x = lo + hi;
    upk2(a1, lo, hi); oA.y = lo + hi;
    upk2(a2, lo, hi); oA.z = lo + hi;
    upk2(a3, lo, hi); oA.w = lo + hi;
    upk2(b0, lo, hi); oB.x = lo + hi;
    upk2(b1, lo, hi); oB.y = lo + hi;
    upk2(b2, lo, hi); oB.z = lo + hi;
    upk2(b3, lo, hi); oB.w = lo + hi;
}

__global__ void __launch_bounds__(256)
k_pass2(const float* __restrict__ x,
        const int* __restrict__ batch,
        const float* __restrict__ W2a,
        const float* __restrict__ W2b,
        const float* __restrict__ b2b,
        float* __restrict__ out,
        int N) {
    __shared__ __align__(16) float sw[(HIDDEN / 2) * 20];
    __shared__ __align__(16) float sx[P2_NODES * NODE_F];
    __shared__ __align__(16) float sG[P2_SGMAX * HIDDEN];

    const int tid = threadIdx.x;
    const long long base = (long long)blockIdx.x * P2_NODES;
    int nmax = N - (int)base; if (nmax > P2_NODES) nmax = P2_NODES;

    // stage weight records
    for (int i = tid; i < (HIDDEN / 2) * 20; i += 256) {
        int p = i / 20, f = i % 20;
        float v = 0.0f;
        int ch = 2 * p + (f & 1);
        if (f < 8)       v = W2a[(f >> 1) * HIDDEN + ch];
        else if (f < 16) v = W2b[ch * OUT_F + ((f - 8) >> 1)];
        else if (f < 18) v = W2a[4 * HIDDEN + ch];
        sw[i] = v;
    }

    // stage x (float4 main + scalar tail)
    {
        int nf  = nmax * NODE_F;
        int nf4 = nf >> 2;
        const float4* xs4 = (const float4*)(x + base * NODE_F);
        float4* sx4 = (float4*)sx;
        for (int i = tid; i < nf4; i += 256) sx4[i] = __ldg(xs4 + i);
        for (int i = nf4 * 4 + tid; i < nf; i += 256) sx[i] = __ldg(x + base * NODE_F + i);
    }

    // graph span + stage G rows
    unsigned g0;
    int rows;
    {
        unsigned ga = (unsigned)__ldg(batch + base);
        unsigned gb = (unsigned)__ldg(batch + base + nmax - 1);
        if (ga >= N_GRAPHS) ga = 0;
        if (gb >= N_GRAPHS) gb = 0;
        g0 = ga;
        int span = (int)gb - (int)ga + 1;
        rows = span < 1 ? 1 : (span > P2_SGMAX ? P2_SGMAX : span);
    }
    if (tid < rows * (HIDDEN / 4)) {
        ((float4*)sG)[tid] = __ldg((const float4*)(g_G + (long long)g0 * HIDDEN) + tid);
    }
    __syncthreads();

    const long long nA = base + tid;
    const long long nB = base + tid + 256;
    if (nA >= N) return;

    float4 bb = __ldg((const float4*)b2b);

    unsigned gA = (unsigned)__ldg(batch + nA);
    if (gA >= N_GRAPHS) gA = 0;
    unsigned relA = gA - g0;

    const float* xsA = sx + tid * NODE_F;
    float4 oA, oB;

    if (nB < N) {
        unsigned gB = (unsigned)__ldg(batch + nB);
        if (gB >= N_GRAPHS) gB = 0;
        unsigned relB = gB - g0;
        const float* xsB = sx + (tid + 256) * NODE_F;

        if (relA < (unsigned)rows && relB < (unsigned)rows) {
            p2_pair(xsA, xsB, sG + relA * HIDDEN, sG + relB * HIDDEN, sw, oA, oB);
        } else {
            p2_pair(xsA, xsB, g_G + (long long)gA * HIDDEN,
                              g_G + (long long)gB * HIDDEN, sw, oA, oB);
        }
        oA.x += bb.x; oA.y += bb.y; oA.z += bb.z; oA.w += bb.w;
        oB.x += bb.x; oB.y += bb.y; oB.z += bb.z; oB.w += bb.w;
        ((float4*)out)[nA] = oA;
        ((float4*)out)[nB] = oB;
    } else {
        if (relA < (unsigned)rows) {
            p2_pair(xsA, xsA, sG + relA * HIDDEN, sG + relA * HIDDEN, sw, oA, oB);
        } else {
            p2_pair(xsA, xsA, g_G + (long long)gA * HIDDEN,
                              g_G + (long long)gA * HIDDEN, sw, oA, oB);
        }
        oA.x += bb.x; oA.y += bb.y; oA.z += bb.z; oA.w += bb.w;
        ((float4*)out)[nA] = oA;
    }
}

// ---------------------------------------------------------------------------
extern "C" void kernel_launch(void* const* d_in, const int* in_sizes, int n_in,
                              void* d_out, int out_size) {
    const float* x     = (const float*)d_in[0];
    const int*   batch = (const int*)d_in[2];     // int32 (JAX x64 disabled)
    int wb = n_in - 8;
    const float* W1a = (const float*)d_in[wb + 0];
    const float* b1a = (const float*)d_in[wb + 1];
    const float* W1b = (const float*)d_in[wb + 2];
    const float* b1b = (const float*)d_in[wb + 3];
    const float* W2a = (const float*)d_in[wb + 4];
    const float* b2a = (const float*)d_in[wb + 5];
    const float* W2b = (const float*)d_in[wb + 6];
    const float* b2b = (const float*)d_in[wb + 7];
    float* out = (float*)d_out;

    int N = in_sizes[0] / NODE_F;

    // K0: zero scratch
    k_zero<<<(N_GRAPHS * HIDDEN + 255) / 256, 256>>>();

    // K1: pass 1 (segment-summed hidden h)
    {
        long long warps = ((long long)N + NPW - 1) / NPW;
        int blocks = (int)((warps * 32 + 255) / 256);
        k_pass1<<<blocks, 256>>>(x, batch, W1a, b1a, N);
    }

    // K2: per-graph GEMMs (b2a folded into G)
    k_graph<<<N_GRAPHS, HIDDEN>>>(W1b, b1b, W2a, b2a);

    // K3: pass 2 (output)
    {
        int blocks = (N + P2_NODES - 1) / P2_NODES;
        k_pass2<<<blocks, 256>>>(x, batch, W2a, W2b, b2b, out, N);
    }
}